// round 15
// baseline (speedup 1.0000x reference)
#include <cuda_runtime.h>
#include <cuda_fp16.h>
#include <cstdint>

#define BB 2
#define NN 20000
#define SS 1024
#define CC 256
#define NSS 16
#define OUTC 96
#define MROWS (BB*SS*NSS)   /* 32768 */
#define K1P 288             /* 259 padded to multiple of 32 */
#define NQ  (BB*SS)         /* 2048 */
#define QPB 8               /* queries per selection CTA */
#define TP  2048            /* xyz points per smem tile */

// fused kernel A block ranges
#define SEL_B  (NQ/QPB)                 /* 256  selection CTAs (first) */
#define PREP_B ((512*K1P+255)/256)      /* 576  prep CTAs */
#define TR_B   ((NN/32)*(CC/64)*BB)     /* 5000 transpose CTAs */

// ---------------- scratch (static device globals; no runtime alloc) --------
__device__ __half g_featT[(size_t)BB*NN*CC];
__device__ __half g_H0[(size_t)MROWS*K1P];
__device__ __half g_act1[(size_t)MROWS*512];
__device__ __half g_act2[(size_t)MROWS*256];
__device__ __half g_act3[(size_t)MROWS*256];
__device__ __half g_w1h[512*K1P];
__device__ __half g_w2h[256*512];
__device__ __half g_w3h[256*256];
__device__ __half g_cw1h[256*256];
__device__ __half g_cw2h[256*256];
__device__ __half g_cw3h[128*256];
__device__ float  g_cb3p[128];
// compaction bookkeeping
__device__ int g_Mtotal;
__device__ int g_qbase[NQ];
__device__ int g_qcnt[NQ];
__device__ int g_rowpt[MROWS];          /* b*NN + point idx per compacted row */

// =============== fused kernel A: selection | prep | transpose ===============
__global__ void __launch_bounds__(256)
fusedA_kernel(const float* __restrict__ xyz, const float* __restrict__ new_xyz,
              const float* __restrict__ view_rot, const float* __restrict__ feat,
              const float* __restrict__ w1, const float* __restrict__ w2,
              const float* __restrict__ w3, const float* __restrict__ cw1,
              const float* __restrict__ cw2, const float* __restrict__ cw3,
              const float* __restrict__ cb3)
{
    __shared__ __align__(16) char sbuf[3 * TP * 4 + QPB * 16 * 4 + QPB * 48 * 4 + 16];
    const int bid = blockIdx.x;
    const int tid = threadIdx.x;

    if (bid < SEL_B) {
        // ---------------- selection (ball query, ordered first-16) ----------
        float* sx = (float*)sbuf;
        float* sy = sx + TP;
        float* sz = sy + TP;
        int*   s_cand = (int*)(sz + TP);             // [QPB][16]
        float* s_co   = (float*)(s_cand + QPB * 16); // [QPB][48]
        int*   s_done = (int*)(s_co + QPB * 48);

        const int lane = tid & 31, w = tid >> 5;
        const int q = bid * QPB + w;
        const int b = q >> 10;

        const float* vr = view_rot + (size_t)q * 9;
        float R00 = vr[0], R01 = vr[1], R02 = vr[2];
        float R10 = vr[3], R11 = vr[4], R12 = vr[5];
        float R20 = vr[6], R21 = vr[7], R22 = vr[8];
        float qx = new_xyz[q * 3 + 0], qy = new_xyz[q * 3 + 1], qz = new_xyz[q * 3 + 2];
        float d0 = R00 * qx + R01 * qy + R02 * qz;
        float d1 = R10 * qx + R11 * qy + R12 * qz;
        float d2 = R20 * qx + R21 * qy + R22 * qz;

        const float* xb = xyz + (size_t)b * NN * 3;

        if (tid == 0) s_done[0] = 0;
        __syncthreads();

        int cnt = 0;
        bool done = false;
        for (int t0 = 0; t0 < NN; t0 += TP) {
            const int npts = (NN - t0 < TP) ? (NN - t0) : TP;
            for (int i = tid; i < npts; i += 256) {
                const float* p = xb + (size_t)(t0 + i) * 3;
                sx[i] = p[0]; sy[i] = p[1]; sz[i] = p[2];
            }
            __syncthreads();
            if (!done) {
                for (int it = 0; it < npts; it += 32) {
                    int i = it + lane;
                    bool mk = false;
                    if (i < npts) {
                        float x = sx[i], y = sy[i], z = sz[i];
                        float xr = fmaf(R00, x, fmaf(R01, y, R02 * z)) - d0;
                        float yr = fmaf(R10, x, fmaf(R11, y, R12 * z)) - d1;
                        float zr = fmaf(R20, x, fmaf(R21, y, R22 * z)) - d2;
                        mk = (yr * yr + zr * zr < 0.05f * 0.05f) && (xr > -0.02f) && (xr < 0.04f);
                    }
                    unsigned bal = __ballot_sync(0xffffffffu, mk);
                    if (bal) {
                        int pos = cnt + __popc(bal & ((1u << lane) - 1u));
                        if (mk && pos < 16) s_cand[w * 16 + pos] = t0 + i;
                        cnt += __popc(bal);
                        if (cnt >= 16) break;
                    }
                }
                if (cnt >= 16) {
                    done = true;
                    if (lane == 0) atomicAdd(s_done, 1);
                }
            }
            __syncthreads();
            if (s_done[0] == QPB) break;
        }

        // per-query compacted allocation
        int f = cnt < 16 ? cnt : 16;
        int K = (f > 0) ? f : 1;
        if (f == 0 && lane == 0) s_cand[w * 16] = 0;
        __syncwarp();
        int base = 0;
        if (lane == 0) {
            base = atomicAdd(&g_Mtotal, K);
            g_qbase[q] = base;
            g_qcnt[q]  = K;
        }
        base = __shfl_sync(0xffffffffu, base, 0);

        if (lane < K) {
            int pidx = s_cand[w * 16 + lane];
            g_rowpt[base + lane] = b * NN + pidx;
            float gx = xb[pidx * 3 + 0], gy = xb[pidx * 3 + 1], gz = xb[pidx * 3 + 2];
            float dx = (gx - qx) / 0.05f;
            float dy = (gy - qy) / 0.05f;
            float dz = (gz - qz) / 0.05f;
            s_co[w * 48 + lane * 3 + 0] = dx * R00 + dy * R10 + dz * R20;
            s_co[w * 48 + lane * 3 + 1] = dx * R01 + dy * R11 + dz * R21;
            s_co[w * 48 + lane * 3 + 2] = dx * R02 + dy * R12 + dz * R22;
        }
        __syncwarp();

        __half* H = g_H0 + (size_t)base * K1P;
        for (int t = lane; t < K * 32; t += 32) {        // cols 256..287
            int n = t >> 5, c = 256 + (t & 31);
            float v = (c < 259) ? s_co[w * 48 + n * 3 + (c - 256)] : 0.f;
            H[(size_t)n * K1P + c] = __float2half(v);
        }
    } else if (bid < SEL_B + PREP_B) {
        // ---------------- weight prep ---------------------------------------
        int i = (bid - SEL_B) * 256 + tid;
        if (i < 512 * K1P) {
            int o = i / K1P, k = i % K1P;
            float v = 0.f;
            if (k < 256)      v = w1[o * 259 + 3 + k];
            else if (k < 259) v = w1[o * 259 + (k - 256)];
            g_w1h[i] = __float2half(v);
        }
        if (i < 256 * 512) g_w2h[i] = __float2half(w2[i]);
        if (i < 256 * 256) {
            g_w3h[i]  = __float2half(w3[i]);
            g_cw1h[i] = __float2half(cw1[i]);
            g_cw2h[i] = __float2half(cw2[i]);
        }
        if (i < 128 * 256) {
            int o = i >> 8, k = i & 255;
            g_cw3h[i] = __float2half(o < OUTC ? cw3[o * 256 + k] : 0.f);
        }
        if (i < 128) g_cb3p[i] = (i < OUTC) ? cb3[i] : 0.f;
    } else {
        // ---------------- transpose features [b][c][n] -> [b][n][c] fp16 ----
        float* tile = (float*)sbuf;                       // [64][33]
        int t = bid - SEL_B - PREP_B;
        int b = t / ((NN / 32) * (CC / 64));
        int r = t % ((NN / 32) * (CC / 64));
        int c0 = (r / (NN / 32)) * 64;
        int n0 = (r % (NN / 32)) * 32;
        int tx = tid & 31, ty = tid >> 5;
        const float* fb = feat + (size_t)b * CC * NN;
#pragma unroll
        for (int i = 0; i < 8; ++i) {
            int c = c0 + ty + i * 8;
            tile[(ty + i * 8) * 33 + tx] = fb[(size_t)c * NN + n0 + tx];
        }
        __syncthreads();
        __half* ft = g_featT + (size_t)b * NN * CC;
#pragma unroll
        for (int i = 0; i < 4; ++i) {
            int n = ty + i * 8;
            __half2 v = __floats2half2_rn(tile[(2 * tx) * 33 + n], tile[(2 * tx + 1) * 33 + n]);
            *(__half2*)(ft + (size_t)(n0 + n) * CC + c0 + 2 * tx) = v;
        }
    }
}

// =============== kernel B: H0 feature fill (coalesced row copies) ===========
__global__ void __launch_bounds__(256)
fillB_kernel()
{
    const int row = blockIdx.x * 8 + (threadIdx.x >> 5);
    if (row >= g_Mtotal) return;
    const int lane = threadIdx.x & 31;
    const __half* src = g_featT + (size_t)g_rowpt[row] * CC + lane * 8;
    __half* dst = g_H0 + (size_t)row * K1P + lane * 8;
    *(uint4*)dst = *(const uint4*)src;
}

// ---------------- tensor-core GEMM (mma.sync path) ---------------------------
__device__ __forceinline__ void ldsm_x4(unsigned& r0, unsigned& r1,
                                        unsigned& r2, unsigned& r3,
                                        const __half* p)
{
    unsigned a = (unsigned)__cvta_generic_to_shared(p);
    asm volatile("ldmatrix.sync.aligned.m8n8.x4.shared.b16 {%0,%1,%2,%3}, [%4];"
                 : "=r"(r0), "=r"(r1), "=r"(r2), "=r"(r3) : "r"(a));
}
__device__ __forceinline__ void mma16816(float* c, const unsigned* a,
                                         unsigned b0, unsigned b1)
{
    asm volatile(
        "mma.sync.aligned.m16n8k16.row.col.f32.f16.f16.f32 "
        "{%0,%1,%2,%3},{%4,%5,%6,%7},{%8,%9},{%0,%1,%2,%3};"
        : "+f"(c[0]), "+f"(c[1]), "+f"(c[2]), "+f"(c[3])
        : "r"(a[0]), "r"(a[1]), "r"(a[2]), "r"(a[3]), "r"(b0), "r"(b1));
}
__device__ __forceinline__ void cp16(void* sdst, const void* gsrc)
{
    unsigned s = (unsigned)__cvta_generic_to_shared(sdst);
    asm volatile("cp.async.cg.shared.global [%0], [%1], 16;" :: "r"(s), "l"(gsrc));
}
__device__ __forceinline__ void cp_commit() { asm volatile("cp.async.commit_group;"); }
template<int N>
__device__ __forceinline__ void cp_wait() { asm volatile("cp.async.wait_group %0;" :: "n"(N)); }

#define STG_A (64*40)     /* A stage: 64 rows x 32 halfs, stride 40 */
#define STG_W (128*40)    /* W stage: 128 rows x 32 halfs, stride 40 */

// CTA tile 64(M) x 128(N), 8 warps (4x2), warp tile 16x64, 3-stage cp.async.
// 3 CTAs/SM (24 warps) for latency hiding.
template<bool OUT_HALF, bool DO_BN>
__global__ void __launch_bounds__(256, 3)
gemm_kernel(const __half* __restrict__ A, int lda,
            const __half* __restrict__ W, int ldw, int K,
            const float* __restrict__ bias, const float* __restrict__ gain,
            const float* __restrict__ beta, void* __restrict__ outp, int ldo,
            const int* __restrict__ mcnt, int nvalid)
{
    const size_t m0 = (size_t)blockIdx.x * 64;
    if (mcnt) {
        int M = (*mcnt + 63) & ~63;
        if ((int)m0 >= M) return;
    }

    extern __shared__ __half dsm[];
    __half* Asb = dsm;                 // 3 stages of STG_A
    __half* Wsb = dsm + 3 * STG_A;     // 3 stages of STG_W

    const int tid = threadIdx.x, lane = tid & 31, warp = tid >> 5;
    const int wm = warp & 3, wn = warp >> 2;
    const int n0 = blockIdx.y * 128;

    float acc[8][4] = {};

    const int lr = tid >> 2;          // 0..63
    const int lc = (tid & 3) * 8;
    const __half* Ag = A + (m0 + lr) * lda + lc;
    const __half* Wg = W + (size_t)(n0 + lr) * ldw + lc;
    const int KT = K >> 5;

#define STAGE_LOAD(st, kt)                                                    \
    {                                                                         \
        const __half* ap = Ag + (kt) * 32;                                    \
        const __half* wp = Wg + (kt) * 32;                                    \
        __half* as = Asb + (st) * STG_A;                                      \
        __half* ws = Wsb + (st) * STG_W;                                      \
        cp16(as + lr * 40 + lc, ap);                                          \
        cp16(ws + lr * 40 + lc, wp);                                          \
        cp16(ws + (lr + 64) * 40 + lc, wp + (size_t)64 * ldw);                \
        cp_commit();                                                          \
    }

    STAGE_LOAD(0, 0)
    STAGE_LOAD(1, 1)

    int st = 0;
    for (int kt = 0; kt < KT; ++kt) {
        if (kt + 1 < KT) cp_wait<1>(); else cp_wait<0>();
        __syncthreads();
        if (kt + 2 < KT) {
            int st2 = st + 2; if (st2 >= 3) st2 -= 3;
            STAGE_LOAD(st2, kt + 2)
        }
        const __half* as = Asb + st * STG_A;
        const __half* ws = Wsb + st * STG_W;
#pragma unroll
        for (int kb = 0; kb < 32; kb += 16) {
            unsigned am[4];
            ldsm_x4(am[0], am[1], am[2], am[3],
                    as + (wm * 16 + (lane & 15)) * 40 + kb + (lane >> 4) * 8);
            unsigned b0[8], b1[8];
#pragma unroll
            for (int p = 0; p < 4; ++p) {
                unsigned t0, t1, t2, t3;
                ldsm_x4(t0, t1, t2, t3,
                        ws + (wn * 64 + p * 16 + (lane & 15)) * 40 + kb + (lane >> 4) * 8);
                b0[2 * p] = t0; b0[2 * p + 1] = t1;
                b1[2 * p] = t2; b1[2 * p + 1] = t3;
            }
#pragma unroll
            for (int ni = 0; ni < 8; ++ni)
                mma16816(acc[ni], am, b0[ni], b1[ni]);
        }
        ++st; if (st == 3) st = 0;
    }

    const float inv = rsqrtf(1.f + 1e-5f);
    {
        size_t row = m0 + wm * 16 + (lane >> 2);
#pragma unroll
        for (int ni = 0; ni < 8; ++ni) {
            int col = n0 + wn * 64 + ni * 8 + (lane & 3) * 2;
            if (col >= nvalid) continue;
            float v00, v01, v10, v11;
            if (DO_BN) {
                float s0 = gain[col] * inv,  s1 = gain[col + 1] * inv;
                float bi0 = bias[col],       bi1 = bias[col + 1];
                float be0 = beta[col],       be1 = beta[col + 1];
                v00 = fmaxf(fmaf(acc[ni][0] + bi0, s0, be0), 0.f);
                v01 = fmaxf(fmaf(acc[ni][1] + bi1, s1, be1), 0.f);
                v10 = fmaxf(fmaf(acc[ni][2] + bi0, s0, be0), 0.f);
                v11 = fmaxf(fmaf(acc[ni][3] + bi1, s1, be1), 0.f);
            } else {
                float bi0 = bias[col], bi1 = bias[col + 1];
                v00 = acc[ni][0] + bi0;  v01 = acc[ni][1] + bi1;
                v10 = acc[ni][2] + bi0;  v11 = acc[ni][3] + bi1;
            }
            if (OUT_HALF) {
                __half* o = (__half*)outp;
                *(__half2*)(o + row * ldo + col)       = __floats2half2_rn(v00, v01);
                *(__half2*)(o + (row + 8) * ldo + col) = __floats2half2_rn(v10, v11);
            } else {
                float* o = (float*)outp;
                *(float2*)(o + row * ldo + col)        = make_float2(v00, v01);
                *(float2*)(o + (row + 8) * ldo + col)  = make_float2(v10, v11);
            }
        }
    }
}

// =============== fused head: maxpool + c1 + c2 + c3 ==========================
// 128 CTAs x 256 thr; 16 queries per CTA (one wave across the chip).
#define HST   (256*40)    /* weight stage: 256 rows x 32 halfs, stride 40 */
#define HABUF (8*16*40)   /* activation buffer: 8 ktiles x 16 rows x 40   */

__global__ void __launch_bounds__(256)
head_fused(const float* __restrict__ cb1, const float* __restrict__ cg1,
           const float* __restrict__ cbe1,
           const float* __restrict__ cb2, const float* __restrict__ cg2,
           const float* __restrict__ cbe2,
           float* __restrict__ out)
{
    extern __shared__ __half hsm[];
    __half* A0 = hsm;
    __half* A1 = hsm + HABUF;
    __half* Ws = hsm + 2 * HABUF;    // 3 stages of HST

    const int tid = threadIdx.x, lane = tid & 31, warp = tid >> 5;
    const int q0 = blockIdx.x * 16;

    // ---- maxpool over compacted act3 rows into A0 (exact fp16 max) ----
    {
        const int kt = lane >> 2;
        const int off = (lane & 3) * 8;
#pragma unroll
        for (int j = 0; j < 2; ++j) {
            int row = warp * 2 + j;
            int q = q0 + row;
            int base = g_qbase[q], K = g_qcnt[q];
            const __half* a = g_act3 + (size_t)base * 256 + lane * 8;
            uint4 v = *(const uint4*)a;
            __half2 m0 = ((const __half2*)&v)[0], m1 = ((const __half2*)&v)[1];
            __half2 m2 = ((const __half2*)&v)[2], m3 = ((const __half2*)&v)[3];
            for (int n = 1; n < K; ++n) {
                uint4 u = *(const uint4*)(a + (size_t)n * 256);
                m0 = __hmax2(m0, ((const __half2*)&u)[0]);
                m1 = __hmax2(m1, ((const __half2*)&u)[1]);
                m2 = __hmax2(m2, ((const __half2*)&u)[2]);
                m3 = __hmax2(m3, ((const __half2*)&u)[3]);
            }
            uint4 pk;
            ((__half2*)&pk)[0] = m0; ((__half2*)&pk)[1] = m1;
            ((__half2*)&pk)[2] = m2; ((__half2*)&pk)[3] = m3;
            *(uint4*)(A0 + (size_t)(kt * 16 + row) * 40 + off) = pk;
        }
    }
    __syncthreads();

    __half* Acur = A0;
    __half* Anx  = A1;
    const int lr = tid >> 2;
    const int lc = (tid & 3) * 8;
    const float inv = rsqrtf(1.f + 1e-5f);

    for (int layer = 0; layer < 3; ++layer) {
        const __half* W = (layer == 0) ? g_cw1h : (layer == 1) ? g_cw2h : g_cw3h;
        const int nrows = (layer == 2) ? 128 : 256;
        float acc[4][4] = {};

#define HSTAGE_LOAD(st, kt)                                                   \
        {                                                                     \
            __half* ws = Ws + (st) * HST;                                     \
            _Pragma("unroll")                                                 \
            for (int ps = 0; ps < 4; ++ps) {                                  \
                int rowi = lr + ps * 64;                                      \
                if (rowi < nrows)                                             \
                    cp16(ws + rowi * 40 + lc, W + (size_t)rowi * 256 + (kt) * 32 + lc); \
            }                                                                 \
            cp_commit();                                                      \
        }

        HSTAGE_LOAD(0, 0)
        HSTAGE_LOAD(1, 1)

        int st = 0;
        for (int kt = 0; kt < 8; ++kt) {
            if (kt + 1 < 8) cp_wait<1>(); else cp_wait<0>();
            __syncthreads();
            if (kt + 2 < 8) {
                int s2 = st + 2; if (s2 >= 3) s2 -= 3;
                HSTAGE_LOAD(s2, kt + 2)
            }
            const __half* ws = Ws + st * HST;
#pragma unroll
            for (int kb = 0; kb < 32; kb += 16) {
                unsigned am[4];
                ldsm_x4(am[0], am[1], am[2], am[3],
                        Acur + (size_t)(kt * 16 + (lane & 15)) * 40
                             + kb + (lane >> 4) * 8);
                unsigned b0[4], b1[4];
#pragma unroll
                for (int p = 0; p < 2; ++p) {
                    unsigned t0, t1, t2, t3;
                    ldsm_x4(t0, t1, t2, t3,
                            ws + (size_t)(warp * 32 + p * 16 + (lane & 15)) * 40
                               + kb + (lane >> 4) * 8);
                    b0[2 * p] = t0; b0[2 * p + 1] = t1;
                    b1[2 * p] = t2; b1[2 * p + 1] = t3;
                }
#pragma unroll
                for (int ni = 0; ni < 4; ++ni)
                    mma16816(acc[ni], am, b0[ni], b1[ni]);
            }
            ++st; if (st == 3) st = 0;
        }

        // epilogue: warp owns cols warp*32 .. warp*32+31, rows 0..15
        const float* bias = (layer == 0) ? cb1 : cb2;
        const float* gain = (layer == 0) ? cg1 : cg2;
        const float* beta = (layer == 0) ? cbe1 : cbe2;
        int row = lane >> 2;
#pragma unroll
        for (int ni = 0; ni < 4; ++ni) {
            int col = warp * 32 + ni * 8 + (lane & 3) * 2;
            if (layer == 2) {
                if (col < OUTC) {
                    float v00 = acc[ni][0] + g_cb3p[col];
                    float v01 = acc[ni][1] + g_cb3p[col + 1];
                    float v10 = acc[ni][2] + g_cb3p[col];
                    float v11 = acc[ni][3] + g_cb3p[col + 1];
                    *(float2*)(out + (size_t)(q0 + row) * OUTC + col)     = make_float2(v00, v01);
                    *(float2*)(out + (size_t)(q0 + row + 8) * OUTC + col) = make_float2(v10, v11);
                }
            } else {
                float s0 = gain[col] * inv,  s1 = gain[col + 1] * inv;
                float bi0 = bias[col],       bi1 = bias[col + 1];
                float be0 = beta[col],       be1 = beta[col + 1];
                float v00 = fmaxf(fmaf(acc[ni][0] + bi0, s0, be0), 0.f);
                float v01 = fmaxf(fmaf(acc[ni][1] + bi1, s1, be1), 0.f);
                float v10 = fmaxf(fmaf(acc[ni][2] + bi0, s0, be0), 0.f);
                float v11 = fmaxf(fmaf(acc[ni][3] + bi1, s1, be1), 0.f);
                size_t o0 = (size_t)((col >> 5) * 16 + row) * 40 + (col & 31);
                *(__half2*)(Anx + o0)          = __floats2half2_rn(v00, v01);
                *(__half2*)(Anx + o0 + 8 * 40) = __floats2half2_rn(v10, v11);
            }
        }
        __syncthreads();
        __half* t = Acur; Acur = Anx; Anx = t;
    }
}

// ---------------- launch ------------------------------------------------------
extern "C" void kernel_launch(void* const* d_in, const int* in_sizes, int n_in,
                              void* d_out, int out_size)
{
    const float* xyz      = (const float*)d_in[0];
    const float* new_xyz  = (const float*)d_in[1];
    const float* view_rot = (const float*)d_in[2];
    const float* features = (const float*)d_in[3];
    const float* w1  = (const float*)d_in[4];
    const float* b1  = (const float*)d_in[5];
    const float* g1  = (const float*)d_in[6];
    const float* be1 = (const float*)d_in[7];
    const float* w2  = (const float*)d_in[8];
    const float* b2  = (const float*)d_in[9];
    const float* g2  = (const float*)d_in[10];
    const float* be2 = (const float*)d_in[11];
    const float* w3  = (const float*)d_in[12];
    const float* b3  = (const float*)d_in[13];
    const float* g3  = (const float*)d_in[14];
    const float* be3 = (const float*)d_in[15];
    const float* cw1 = (const float*)d_in[16];
    const float* cb1 = (const float*)d_in[17];
    const float* cg1 = (const float*)d_in[18];
    const float* cbe1= (const float*)d_in[19];
    const float* cw2 = (const float*)d_in[20];
    const float* cb2 = (const float*)d_in[21];
    const float* cg2 = (const float*)d_in[22];
    const float* cbe2= (const float*)d_in[23];
    const float* cw3 = (const float*)d_in[24];
    const float* cb3 = (const float*)d_in[25];
    float* out = (float*)d_out;

    __half *h0, *a1, *a2, *a3;
    __half *w1h, *w2h, *w3h;
    int *mtot;
    cudaGetSymbolAddress((void**)&h0,   g_H0);
    cudaGetSymbolAddress((void**)&a1,   g_act1);
    cudaGetSymbolAddress((void**)&a2,   g_act2);
    cudaGetSymbolAddress((void**)&a3,   g_act3);
    cudaGetSymbolAddress((void**)&w1h,  g_w1h);
    cudaGetSymbolAddress((void**)&w2h,  g_w2h);
    cudaGetSymbolAddress((void**)&w3h,  g_w3h);
    cudaGetSymbolAddress((void**)&mtot, g_Mtotal);

    const int SMEM  = 3 * (STG_A + STG_W) * 2;       // 46080 bytes
    const int HSMEM = (2 * HABUF + 3 * HST) * 2;     // 71680 bytes
    cudaFuncSetAttribute(gemm_kernel<true, true>, cudaFuncAttributeMaxDynamicSharedMemorySize, SMEM);
    cudaFuncSetAttribute(head_fused, cudaFuncAttributeMaxDynamicSharedMemorySize, HSMEM);

    cudaMemsetAsync(mtot, 0, sizeof(int));

    fusedA_kernel<<<SEL_B + PREP_B + TR_B, 256>>>(
        xyz, new_xyz, view_rot, features, w1, w2, w3, cw1, cw2, cw3, cb3);
    fillB_kernel<<<MROWS / 8, 256>>>();

    // main MLP chain (compacted rows; CTAs past count exit)
    gemm_kernel<true, true><<<dim3(MROWS / 64, 4), 256, SMEM>>>(h0, K1P, w1h, K1P, K1P, b1, g1, be1, a1, 512, mtot, 512);
    gemm_kernel<true, true><<<dim3(MROWS / 64, 2), 256, SMEM>>>(a1, 512, w2h, 512, 512, b2, g2, be2, a2, 256, mtot, 256);
    gemm_kernel<true, true><<<dim3(MROWS / 64, 2), 256, SMEM>>>(a2, 256, w3h, 256, 256, b3, g3, be3, a3, 256, mtot, 256);

    // fused head: maxpool + c1 + c2 + c3 -> out (16 queries per CTA, 128 CTAs)
    head_fused<<<NQ / 16, 256, HSMEM>>>(cb1, cg1, cbe1, cb2, cg2, cbe2, out);
}

// round 16
// speedup vs baseline: 1.0865x; 1.0865x over previous
#include <cuda_runtime.h>
#include <cuda_fp16.h>
#include <cstdint>

#define BB 2
#define NN 20000
#define SS 1024
#define CC 256
#define NSS 16
#define OUTC 96
#define MROWS (BB*SS*NSS)   /* 32768 */
#define K1P 288             /* 259 padded to multiple of 32 */
#define NQ  (BB*SS)         /* 2048 */
#define QPB 8               /* queries per selection CTA */
#define TP  2048            /* xyz points per smem tile */

// fused kernel A block ranges
#define SEL_B  (NQ/QPB)                 /* 256  selection CTAs (first) */
#define PREP_B ((512*K1P+255)/256)      /* 576  prep CTAs */
#define TR_B   ((NN/32)*(CC/64)*BB)     /* 5000 transpose CTAs */

// ---------------- scratch (static device globals; no runtime alloc) --------
__device__ __half g_featT[(size_t)BB*NN*CC];
__device__ __half g_H0[(size_t)MROWS*K1P];
__device__ __half g_act1[(size_t)MROWS*512];
__device__ __half g_act2[(size_t)MROWS*256];
__device__ __half g_act3[(size_t)MROWS*256];
__device__ __half g_w1h[512*K1P];
__device__ __half g_w2h[256*512];
__device__ __half g_w3h[256*256];
__device__ __half g_cw1h[256*256];
__device__ __half g_cw2h[256*256];
__device__ __half g_cw3h[128*256];
__device__ float  g_cb3p[128];
// compaction bookkeeping (g_Mtotal zero-initialized; head_fused resets it)
__device__ int g_Mtotal;
__device__ int g_qbase[NQ];
__device__ int g_qcnt[NQ];
__device__ int g_rowpt[MROWS];          /* b*NN + point idx per compacted row */

// =============== fused kernel A: selection | prep | transpose ===============
__global__ void __launch_bounds__(256)
fusedA_kernel(const float* __restrict__ xyz, const float* __restrict__ new_xyz,
              const float* __restrict__ view_rot, const float* __restrict__ feat,
              const float* __restrict__ w1, const float* __restrict__ w2,
              const float* __restrict__ w3, const float* __restrict__ cw1,
              const float* __restrict__ cw2, const float* __restrict__ cw3,
              const float* __restrict__ cb3)
{
    __shared__ __align__(16) char sbuf[3 * TP * 4 + QPB * 16 * 4 + QPB * 48 * 4 + 16];
    const int bid = blockIdx.x;
    const int tid = threadIdx.x;

    if (bid < SEL_B) {
        // ---------------- selection (ball query, ordered first-16) ----------
        float* sx = (float*)sbuf;
        float* sy = sx + TP;
        float* sz = sy + TP;
        int*   s_cand = (int*)(sz + TP);             // [QPB][16]
        float* s_co   = (float*)(s_cand + QPB * 16); // [QPB][48]
        int*   s_done = (int*)(s_co + QPB * 48);

        const int lane = tid & 31, w = tid >> 5;
        const int q = bid * QPB + w;
        const int b = q >> 10;

        const float* vr = view_rot + (size_t)q * 9;
        float R00 = vr[0], R01 = vr[1], R02 = vr[2];
        float R10 = vr[3], R11 = vr[4], R12 = vr[5];
        float R20 = vr[6], R21 = vr[7], R22 = vr[8];
        float qx = new_xyz[q * 3 + 0], qy = new_xyz[q * 3 + 1], qz = new_xyz[q * 3 + 2];
        float d0 = R00 * qx + R01 * qy + R02 * qz;
        float d1 = R10 * qx + R11 * qy + R12 * qz;
        float d2 = R20 * qx + R21 * qy + R22 * qz;

        const float* xb = xyz + (size_t)b * NN * 3;

        if (tid == 0) s_done[0] = 0;
        __syncthreads();

        int cnt = 0;
        bool done = false;
        for (int t0 = 0; t0 < NN; t0 += TP) {
            const int npts = (NN - t0 < TP) ? (NN - t0) : TP;
            for (int i = tid; i < npts; i += 256) {
                const float* p = xb + (size_t)(t0 + i) * 3;
                sx[i] = p[0]; sy[i] = p[1]; sz[i] = p[2];
            }
            __syncthreads();
            if (!done) {
                for (int it = 0; it < npts; it += 32) {
                    int i = it + lane;
                    bool mk = false;
                    if (i < npts) {
                        float x = sx[i], y = sy[i], z = sz[i];
                        float xr = fmaf(R00, x, fmaf(R01, y, R02 * z)) - d0;
                        float yr = fmaf(R10, x, fmaf(R11, y, R12 * z)) - d1;
                        float zr = fmaf(R20, x, fmaf(R21, y, R22 * z)) - d2;
                        mk = (yr * yr + zr * zr < 0.05f * 0.05f) && (xr > -0.02f) && (xr < 0.04f);
                    }
                    unsigned bal = __ballot_sync(0xffffffffu, mk);
                    if (bal) {
                        int pos = cnt + __popc(bal & ((1u << lane) - 1u));
                        if (mk && pos < 16) s_cand[w * 16 + pos] = t0 + i;
                        cnt += __popc(bal);
                        if (cnt >= 16) break;
                    }
                }
                if (cnt >= 16) {
                    done = true;
                    if (lane == 0) atomicAdd(s_done, 1);
                }
            }
            __syncthreads();
            if (s_done[0] == QPB) break;
        }

        // per-query compacted allocation
        int f = cnt < 16 ? cnt : 16;
        int K = (f > 0) ? f : 1;
        if (f == 0 && lane == 0) s_cand[w * 16] = 0;
        __syncwarp();
        int base = 0;
        if (lane == 0) {
            base = atomicAdd(&g_Mtotal, K);
            g_qbase[q] = base;
            g_qcnt[q]  = K;
        }
        base = __shfl_sync(0xffffffffu, base, 0);

        if (lane < K) {
            int pidx = s_cand[w * 16 + lane];
            g_rowpt[base + lane] = b * NN + pidx;
            float gx = xb[pidx * 3 + 0], gy = xb[pidx * 3 + 1], gz = xb[pidx * 3 + 2];
            float dx = (gx - qx) / 0.05f;
            float dy = (gy - qy) / 0.05f;
            float dz = (gz - qz) / 0.05f;
            s_co[w * 48 + lane * 3 + 0] = dx * R00 + dy * R10 + dz * R20;
            s_co[w * 48 + lane * 3 + 1] = dx * R01 + dy * R11 + dz * R21;
            s_co[w * 48 + lane * 3 + 2] = dx * R02 + dy * R12 + dz * R22;
        }
        __syncwarp();

        __half* H = g_H0 + (size_t)base * K1P;
        for (int t = lane; t < K * 32; t += 32) {        // cols 256..287
            int n = t >> 5, c = 256 + (t & 31);
            float v = (c < 259) ? s_co[w * 48 + n * 3 + (c - 256)] : 0.f;
            H[(size_t)n * K1P + c] = __float2half(v);
        }
    } else if (bid < SEL_B + PREP_B) {
        // ---------------- weight prep ---------------------------------------
        int i = (bid - SEL_B) * 256 + tid;
        if (i < 512 * K1P) {
            int o = i / K1P, k = i % K1P;
            float v = 0.f;
            if (k < 256)      v = w1[o * 259 + 3 + k];
            else if (k < 259) v = w1[o * 259 + (k - 256)];
            g_w1h[i] = __float2half(v);
        }
        if (i < 256 * 512) g_w2h[i] = __float2half(w2[i]);
        if (i < 256 * 256) {
            g_w3h[i]  = __float2half(w3[i]);
            g_cw1h[i] = __float2half(cw1[i]);
            g_cw2h[i] = __float2half(cw2[i]);
        }
        if (i < 128 * 256) {
            int o = i >> 8, k = i & 255;
            g_cw3h[i] = __float2half(o < OUTC ? cw3[o * 256 + k] : 0.f);
        }
        if (i < 128) g_cb3p[i] = (i < OUTC) ? cb3[i] : 0.f;
    } else {
        // ---------------- transpose features [b][c][n] -> [b][n][c] fp16 ----
        float* tile = (float*)sbuf;                       // [64][33]
        int t = bid - SEL_B - PREP_B;
        int b = t / ((NN / 32) * (CC / 64));
        int r = t % ((NN / 32) * (CC / 64));
        int c0 = (r / (NN / 32)) * 64;
        int n0 = (r % (NN / 32)) * 32;
        int tx = tid & 31, ty = tid >> 5;
        const float* fb = feat + (size_t)b * CC * NN;
#pragma unroll
        for (int i = 0; i < 8; ++i) {
            int c = c0 + ty + i * 8;
            tile[(ty + i * 8) * 33 + tx] = fb[(size_t)c * NN + n0 + tx];
        }
        __syncthreads();
        __half* ft = g_featT + (size_t)b * NN * CC;
#pragma unroll
        for (int i = 0; i < 4; ++i) {
            int n = ty + i * 8;
            __half2 v = __floats2half2_rn(tile[(2 * tx) * 33 + n], tile[(2 * tx + 1) * 33 + n]);
            *(__half2*)(ft + (size_t)(n0 + n) * CC + c0 + 2 * tx) = v;
        }
    }
}

// =============== kernel B: H0 feature fill (coalesced row copies) ===========
__global__ void __launch_bounds__(512)
fillB_kernel()
{
    const int row = blockIdx.x * 16 + (threadIdx.x >> 5);
    if (row >= g_Mtotal) return;
    const int lane = threadIdx.x & 31;
    const __half* src = g_featT + (size_t)g_rowpt[row] * CC + lane * 8;
    __half* dst = g_H0 + (size_t)row * K1P + lane * 8;
    *(uint4*)dst = *(const uint4*)src;
}

// ---------------- tensor-core GEMM (mma.sync path) ---------------------------
__device__ __forceinline__ void ldsm_x4(unsigned& r0, unsigned& r1,
                                        unsigned& r2, unsigned& r3,
                                        const __half* p)
{
    unsigned a = (unsigned)__cvta_generic_to_shared(p);
    asm volatile("ldmatrix.sync.aligned.m8n8.x4.shared.b16 {%0,%1,%2,%3}, [%4];"
                 : "=r"(r0), "=r"(r1), "=r"(r2), "=r"(r3) : "r"(a));
}
__device__ __forceinline__ void mma16816(float* c, const unsigned* a,
                                         unsigned b0, unsigned b1)
{
    asm volatile(
        "mma.sync.aligned.m16n8k16.row.col.f32.f16.f16.f32 "
        "{%0,%1,%2,%3},{%4,%5,%6,%7},{%8,%9},{%0,%1,%2,%3};"
        : "+f"(c[0]), "+f"(c[1]), "+f"(c[2]), "+f"(c[3])
        : "r"(a[0]), "r"(a[1]), "r"(a[2]), "r"(a[3]), "r"(b0), "r"(b1));
}
__device__ __forceinline__ void cp16(void* sdst, const void* gsrc)
{
    unsigned s = (unsigned)__cvta_generic_to_shared(sdst);
    asm volatile("cp.async.cg.shared.global [%0], [%1], 16;" :: "r"(s), "l"(gsrc));
}
__device__ __forceinline__ void cp_commit() { asm volatile("cp.async.commit_group;"); }
template<int N>
__device__ __forceinline__ void cp_wait() { asm volatile("cp.async.wait_group %0;" :: "n"(N)); }

#define STG_F (128*40)

// CTA 128x128, 8 warps (4x2), warp tile 32x64, 3-stage cp.async pipeline.
template<bool OUT_HALF, bool DO_BN>
__global__ void __launch_bounds__(256, 2)
gemm_kernel(const __half* __restrict__ A, int lda,
            const __half* __restrict__ W, int ldw, int K,
            const float* __restrict__ bias, const float* __restrict__ gain,
            const float* __restrict__ beta, void* __restrict__ outp, int ldo,
            const int* __restrict__ mcnt)
{
    const size_t m0 = (size_t)blockIdx.x * 128;
    if (mcnt) {
        int M = (*mcnt + 127) & ~127;
        if ((int)m0 >= M) return;
    }

    extern __shared__ __half dsm[];
    __half* Asb = dsm;
    __half* Wsb = dsm + 3 * STG_F;

    const int tid = threadIdx.x, lane = tid & 31, warp = tid >> 5;
    const int wm = warp & 3, wn = warp >> 2;
    const int n0 = blockIdx.y * 128;

    float acc[2][8][4] = {};

    const int lr = tid >> 2;          // 0..63
    const int lc = (tid & 3) * 8;
    const __half* Ag = A + (m0 + lr) * lda + lc;
    const __half* Wg = W + (size_t)(n0 + lr) * ldw + lc;
    const int KT = K >> 5;

#define STAGE_LOAD(st, kt)                                                    \
    {                                                                         \
        const __half* ap = Ag + (kt) * 32;                                    \
        const __half* wp = Wg + (kt) * 32;                                    \
        __half* as = Asb + (st) * STG_F;                                      \
        __half* ws = Wsb + (st) * STG_F;                                      \
        _Pragma("unroll")                                                     \
        for (int ps = 0; ps < 2; ++ps) {                                      \
            cp16(as + (lr + ps * 64) * 40 + lc, ap + (size_t)(ps * 64) * lda);\
            cp16(ws + (lr + ps * 64) * 40 + lc, wp + (size_t)(ps * 64) * ldw);\
        }                                                                     \
        cp_commit();                                                          \
    }

    STAGE_LOAD(0, 0)
    STAGE_LOAD(1, 1)

    int st = 0;
    for (int kt = 0; kt < KT; ++kt) {
        if (kt + 1 < KT) cp_wait<1>(); else cp_wait<0>();
        __syncthreads();
        if (kt + 2 < KT) {
            int st2 = st + 2; if (st2 >= 3) st2 -= 3;
            STAGE_LOAD(st2, kt + 2)
        }
        const __half* as = Asb + st * STG_F;
        const __half* ws = Wsb + st * STG_F;
#pragma unroll
        for (int kb = 0; kb < 32; kb += 16) {
            unsigned am[2][4];
#pragma unroll
            for (int mi = 0; mi < 2; ++mi)
                ldsm_x4(am[mi][0], am[mi][1], am[mi][2], am[mi][3],
                        as + (wm * 32 + mi * 16 + (lane & 15)) * 40 + kb + (lane >> 4) * 8);
            unsigned b0[8], b1[8];
#pragma unroll
            for (int p = 0; p < 4; ++p) {
                unsigned t0, t1, t2, t3;
                ldsm_x4(t0, t1, t2, t3,
                        ws + (wn * 64 + p * 16 + (lane & 15)) * 40 + kb + (lane >> 4) * 8);
                b0[2 * p] = t0; b0[2 * p + 1] = t1;
                b1[2 * p] = t2; b1[2 * p + 1] = t3;
            }
#pragma unroll
            for (int mi = 0; mi < 2; ++mi)
#pragma unroll
                for (int ni = 0; ni < 8; ++ni)
                    mma16816(acc[mi][ni], am[mi], b0[ni], b1[ni]);
        }
        ++st; if (st == 3) st = 0;
    }

    const float inv = rsqrtf(1.f + 1e-5f);
#pragma unroll
    for (int mi = 0; mi < 2; ++mi) {
        size_t row = m0 + wm * 32 + mi * 16 + (lane >> 2);
#pragma unroll
        for (int ni = 0; ni < 8; ++ni) {
            int col = n0 + wn * 64 + ni * 8 + (lane & 3) * 2;
            float v00, v01, v10, v11;
            if (DO_BN) {
                float s0 = gain[col] * inv,  s1 = gain[col + 1] * inv;
                float bi0 = bias[col],       bi1 = bias[col + 1];
                float be0 = beta[col],       be1 = beta[col + 1];
                v00 = fmaxf(fmaf(acc[mi][ni][0] + bi0, s0, be0), 0.f);
                v01 = fmaxf(fmaf(acc[mi][ni][1] + bi1, s1, be1), 0.f);
                v10 = fmaxf(fmaf(acc[mi][ni][2] + bi0, s0, be0), 0.f);
                v11 = fmaxf(fmaf(acc[mi][ni][3] + bi1, s1, be1), 0.f);
            } else {
                float bi0 = bias[col], bi1 = bias[col + 1];
                v00 = acc[mi][ni][0] + bi0;  v01 = acc[mi][ni][1] + bi1;
                v10 = acc[mi][ni][2] + bi0;  v11 = acc[mi][ni][3] + bi1;
            }
            if (OUT_HALF) {
                __half* o = (__half*)outp;
                *(__half2*)(o + row * ldo + col)       = __floats2half2_rn(v00, v01);
                *(__half2*)(o + (row + 8) * ldo + col) = __floats2half2_rn(v10, v11);
            } else {
                float* o = (float*)outp;
                *(float2*)(o + row * ldo + col)        = make_float2(v00, v01);
                *(float2*)(o + (row + 8) * ldo + col)  = make_float2(v10, v11);
            }
        }
    }
}

// =============== fused head: maxpool + c1 + c2 + c3 ==========================
// 128 CTAs x 256 thr; 16 queries per CTA (one wave across the chip).
#define HST   (256*40)    /* weight stage: 256 rows x 32 halfs, stride 40 */
#define HABUF (8*16*40)   /* activation buffer: 8 ktiles x 16 rows x 40   */

__global__ void __launch_bounds__(256)
head_fused(const float* __restrict__ cb1, const float* __restrict__ cg1,
           const float* __restrict__ cbe1,
           const float* __restrict__ cb2, const float* __restrict__ cg2,
           const float* __restrict__ cbe2,
           float* __restrict__ out)
{
    extern __shared__ __half hsm[];
    __half* A0 = hsm;
    __half* A1 = hsm + HABUF;
    __half* Ws = hsm + 2 * HABUF;    // 3 stages of HST

    const int tid = threadIdx.x, lane = tid & 31, warp = tid >> 5;
    const int q0 = blockIdx.x * 16;

    // reset compaction counter for next graph replay (no consumer after gemm3)
    if (blockIdx.x == 0 && tid == 0) g_Mtotal = 0;

    // ---- maxpool over compacted act3 rows into A0 (exact fp16 max) ----
    {
        const int kt = lane >> 2;
        const int off = (lane & 3) * 8;
#pragma unroll
        for (int j = 0; j < 2; ++j) {
            int row = warp * 2 + j;
            int q = q0 + row;
            int base = g_qbase[q], K = g_qcnt[q];
            const __half* a = g_act3 + (size_t)base * 256 + lane * 8;
            uint4 v = *(const uint4*)a;
            __half2 m0 = ((const __half2*)&v)[0], m1 = ((const __half2*)&v)[1];
            __half2 m2 = ((const __half2*)&v)[2], m3 = ((const __half2*)&v)[3];
            for (int n = 1; n < K; ++n) {
                uint4 u = *(const uint4*)(a + (size_t)n * 256);
                m0 = __hmax2(m0, ((const __half2*)&u)[0]);
                m1 = __hmax2(m1, ((const __half2*)&u)[1]);
                m2 = __hmax2(m2, ((const __half2*)&u)[2]);
                m3 = __hmax2(m3, ((const __half2*)&u)[3]);
            }
            uint4 pk;
            ((__half2*)&pk)[0] = m0; ((__half2*)&pk)[1] = m1;
            ((__half2*)&pk)[2] = m2; ((__half2*)&pk)[3] = m3;
            *(uint4*)(A0 + (size_t)(kt * 16 + row) * 40 + off) = pk;
        }
    }
    __syncthreads();

    __half* Acur = A0;
    __half* Anx  = A1;
    const int lr = tid >> 2;
    const int lc = (tid & 3) * 8;
    const float inv = rsqrtf(1.f + 1e-5f);

    for (int layer = 0; layer < 3; ++layer) {
        const __half* W = (layer == 0) ? g_cw1h : (layer == 1) ? g_cw2h : g_cw3h;
        const int nrows = (layer == 2) ? 128 : 256;
        float acc[4][4] = {};

#define HSTAGE_LOAD(st, kt)                                                   \
        {                                                                     \
            __half* ws = Ws + (st) * HST;                                     \
            _Pragma("unroll")                                                 \
            for (int ps = 0; ps < 4; ++ps) {                                  \
                int rowi = lr + ps * 64;                                      \
                if (rowi < nrows)                                             \
                    cp16(ws + rowi * 40 + lc, W + (size_t)rowi * 256 + (kt) * 32 + lc); \
            }                                                                 \
            cp_commit();                                                      \
        }

        HSTAGE_LOAD(0, 0)
        HSTAGE_LOAD(1, 1)

        int st = 0;
        for (int kt = 0; kt < 8; ++kt) {
            if (kt + 1 < 8) cp_wait<1>(); else cp_wait<0>();
            __syncthreads();
            if (kt + 2 < 8) {
                int s2 = st + 2; if (s2 >= 3) s2 -= 3;
                HSTAGE_LOAD(s2, kt + 2)
            }
            const __half* ws = Ws + st * HST;
#pragma unroll
            for (int kb = 0; kb < 32; kb += 16) {
                unsigned am[4];
                ldsm_x4(am[0], am[1], am[2], am[3],
                        Acur + (size_t)(kt * 16 + (lane & 15)) * 40
                             + kb + (lane >> 4) * 8);
                unsigned b0[4], b1[4];
#pragma unroll
                for (int p = 0; p < 2; ++p) {
                    unsigned t0, t1, t2, t3;
                    ldsm_x4(t0, t1, t2, t3,
                            ws + (size_t)(warp * 32 + p * 16 + (lane & 15)) * 40
                               + kb + (lane >> 4) * 8);
                    b0[2 * p] = t0; b0[2 * p + 1] = t1;
                    b1[2 * p] = t2; b1[2 * p + 1] = t3;
                }
#pragma unroll
                for (int ni = 0; ni < 4; ++ni)
                    mma16816(acc[ni], am, b0[ni], b1[ni]);
            }
            ++st; if (st == 3) st = 0;
        }

        // epilogue: warp owns cols warp*32 .. warp*32+31, rows 0..15
        const float* bias = (layer == 0) ? cb1 : cb2;
        const float* gain = (layer == 0) ? cg1 : cg2;
        const float* beta = (layer == 0) ? cbe1 : cbe2;
        int row = lane >> 2;
#pragma unroll
        for (int ni = 0; ni < 4; ++ni) {
            int col = warp * 32 + ni * 8 + (lane & 3) * 2;
            if (layer == 2) {
                if (col < OUTC) {
                    float v00 = acc[ni][0] + g_cb3p[col];
                    float v01 = acc[ni][1] + g_cb3p[col + 1];
                    float v10 = acc[ni][2] + g_cb3p[col];
                    float v11 = acc[ni][3] + g_cb3p[col + 1];
                    *(float2*)(out + (size_t)(q0 + row) * OUTC + col)     = make_float2(v00, v01);
                    *(float2*)(out + (size_t)(q0 + row + 8) * OUTC + col) = make_float2(v10, v11);
                }
            } else {
                float s0 = gain[col] * inv,  s1 = gain[col + 1] * inv;
                float bi0 = bias[col],       bi1 = bias[col + 1];
                float be0 = beta[col],       be1 = beta[col + 1];
                float v00 = fmaxf(fmaf(acc[ni][0] + bi0, s0, be0), 0.f);
                float v01 = fmaxf(fmaf(acc[ni][1] + bi1, s1, be1), 0.f);
                float v10 = fmaxf(fmaf(acc[ni][2] + bi0, s0, be0), 0.f);
                float v11 = fmaxf(fmaf(acc[ni][3] + bi1, s1, be1), 0.f);
                size_t o0 = (size_t)((col >> 5) * 16 + row) * 40 + (col & 31);
                *(__half2*)(Anx + o0)          = __floats2half2_rn(v00, v01);
                *(__half2*)(Anx + o0 + 8 * 40) = __floats2half2_rn(v10, v11);
            }
        }
        __syncthreads();
        __half* t = Acur; Acur = Anx; Anx = t;
    }
}

// ---------------- launch ------------------------------------------------------
extern "C" void kernel_launch(void* const* d_in, const int* in_sizes, int n_in,
                              void* d_out, int out_size)
{
    const float* xyz      = (const float*)d_in[0];
    const float* new_xyz  = (const float*)d_in[1];
    const float* view_rot = (const float*)d_in[2];
    const float* features = (const float*)d_in[3];
    const float* w1  = (const float*)d_in[4];
    const float* b1  = (const float*)d_in[5];
    const float* g1  = (const float*)d_in[6];
    const float* be1 = (const float*)d_in[7];
    const float* w2  = (const float*)d_in[8];
    const float* b2  = (const float*)d_in[9];
    const float* g2  = (const float*)d_in[10];
    const float* be2 = (const float*)d_in[11];
    const float* w3  = (const float*)d_in[12];
    const float* b3  = (const float*)d_in[13];
    const float* g3  = (const float*)d_in[14];
    const float* be3 = (const float*)d_in[15];
    const float* cw1 = (const float*)d_in[16];
    const float* cb1 = (const float*)d_in[17];
    const float* cg1 = (const float*)d_in[18];
    const float* cbe1= (const float*)d_in[19];
    const float* cw2 = (const float*)d_in[20];
    const float* cb2 = (const float*)d_in[21];
    const float* cg2 = (const float*)d_in[22];
    const float* cbe2= (const float*)d_in[23];
    const float* cw3 = (const float*)d_in[24];
    const float* cb3 = (const float*)d_in[25];
    float* out = (float*)d_out;

    __half *h0, *a1, *a2, *a3;
    __half *w1h, *w2h, *w3h;
    int *mtot;
    cudaGetSymbolAddress((void**)&h0,   g_H0);
    cudaGetSymbolAddress((void**)&a1,   g_act1);
    cudaGetSymbolAddress((void**)&a2,   g_act2);
    cudaGetSymbolAddress((void**)&a3,   g_act3);
    cudaGetSymbolAddress((void**)&w1h,  g_w1h);
    cudaGetSymbolAddress((void**)&w2h,  g_w2h);
    cudaGetSymbolAddress((void**)&w3h,  g_w3h);
    cudaGetSymbolAddress((void**)&mtot, g_Mtotal);

    const int SMEM  = 6 * STG_F * 2;                 // 61440 bytes
    const int HSMEM = (2 * HABUF + 3 * HST) * 2;     // 71680 bytes
    cudaFuncSetAttribute(gemm_kernel<true, true>, cudaFuncAttributeMaxDynamicSharedMemorySize, SMEM);
    cudaFuncSetAttribute(head_fused, cudaFuncAttributeMaxDynamicSharedMemorySize, HSMEM);

    fusedA_kernel<<<SEL_B + PREP_B + TR_B, 256>>>(
        xyz, new_xyz, view_rot, features, w1, w2, w3, cw1, cw2, cw3, cb3);
    fillB_kernel<<<MROWS / 16, 512>>>();

    // main MLP chain (compacted rows; CTAs past count exit)
    gemm_kernel<true, true><<<dim3(MROWS / 128, 4), 256, SMEM>>>(h0, K1P, w1h, K1P, K1P, b1, g1, be1, a1, 512, mtot);
    gemm_kernel<true, true><<<dim3(MROWS / 128, 2), 256, SMEM>>>(a1, 512, w2h, 512, 512, b2, g2, be2, a2, 256, mtot);
    gemm_kernel<true, true><<<dim3(MROWS / 128, 2), 256, SMEM>>>(a2, 256, w3h, 256, 256, b3, g3, be3, a3, 256, mtot);

    // fused head: maxpool + c1 + c2 + c3 -> out (16 queries per CTA, 128 CTAs)
    head_fused<<<NQ / 16, 256, HSMEM>>>(cb1, cg1, cbe1, cb2, cg2, cbe2, out);
}